// round 5
// baseline (speedup 1.0000x reference)
#include <cuda_runtime.h>
#include <math_constants.h>
#include <cstdint>

// WorkingMemory, algebraic form:
//   w_i = e_i*(S-e_i), e_i = exp(attn_i - mx);  ssq = sum e_i^2
//   r{0,1}[b,c] = 2*mx + log( sum_i w_i*exp(m{0,1}[b,i,c]) + exp(v{0,1}[b,c])*ssq )
// R5: cp.async smem pipeline; SROW 76->68 so static smem = ~27.7KB (<48KB limit,
//     4 CTAs/SM resident).

#define BB 1024
#define AA 512
#define CC 64
#define DD 10
#define NTH 512
#define NWARP 16
#define ROWS_PER_STAGE 16
#define NSTAGE 32          // AA / ROWS_PER_STAGE
#define NBUF 3
#define SROW 68            // padded row stride (272B = 17*16B: aligned, conflict-free)

__device__ __forceinline__ float blockReduceMax(float v, float* sbuf) {
    #pragma unroll
    for (int o = 16; o; o >>= 1) v = fmaxf(v, __shfl_xor_sync(0xffffffffu, v, o));
    int warp = threadIdx.x >> 5;
    if ((threadIdx.x & 31) == 0) sbuf[warp] = v;
    __syncthreads();
    if (threadIdx.x < 32) {
        float x = (threadIdx.x < NWARP) ? sbuf[threadIdx.x] : -CUDART_INF_F;
        #pragma unroll
        for (int o = 8; o; o >>= 1) x = fmaxf(x, __shfl_xor_sync(0xffffffffu, x, o));
        if (threadIdx.x == 0) sbuf[0] = x;
    }
    __syncthreads();
    float r = sbuf[0];
    __syncthreads();
    return r;
}

__device__ __forceinline__ float blockReduceSum(float v, float* sbuf) {
    #pragma unroll
    for (int o = 16; o; o >>= 1) v += __shfl_xor_sync(0xffffffffu, v, o);
    int warp = threadIdx.x >> 5;
    if ((threadIdx.x & 31) == 0) sbuf[warp] = v;
    __syncthreads();
    if (threadIdx.x < 32) {
        float x = (threadIdx.x < NWARP) ? sbuf[threadIdx.x] : 0.0f;
        #pragma unroll
        for (int o = 8; o; o >>= 1) x += __shfl_xor_sync(0xffffffffu, x, o);
        if (threadIdx.x == 0) sbuf[0] = x;
    }
    __syncthreads();
    float r = sbuf[0];
    __syncthreads();
    return r;
}

__device__ __forceinline__ uint32_t smem_u32(const void* p) {
    uint32_t a;
    asm("{ .reg .u64 t; cvta.to.shared.u64 t, %1; cvt.u32.u64 %0, t; }" : "=r"(a) : "l"(p));
    return a;
}
__device__ __forceinline__ void cp16(uint32_t dst, const float* src) {
    asm volatile("cp.async.cg.shared.global [%0], [%1], 16;\n" :: "r"(dst), "l"(src));
}
__device__ __forceinline__ void cp_commit() {
    asm volatile("cp.async.commit_group;\n" ::: "memory");
}
__device__ __forceinline__ void cp_wait1() {
    asm volatile("cp.async.wait_group 1;\n" ::: "memory");
}
__device__ __forceinline__ void cp_wait0() {
    asm volatile("cp.async.wait_group 0;\n" ::: "memory");
}

__global__ __launch_bounds__(NTH, 4)
void wm_kernel(const float* __restrict__ m0, const float* __restrict__ m1,
               const float* __restrict__ a0, const float* __restrict__ a1,
               const float* __restrict__ v0, const float* __restrict__ v1,
               float* __restrict__ out)
{
    __shared__ float sred[32];
    __shared__ float sw[AA];
    __shared__ __align__(16) float buf[NBUF][2][ROWS_PER_STAGE][SROW];

    const int b   = blockIdx.x;
    const int tid = threadIdx.x;

    // -------- loader mapping: thread t loads one 16B chunk per stage --------
    const int lm    = tid >> 8;          // which matrix this thread loads
    const int u     = tid & 255;
    const int lrow  = u >> 4;            // row-in-stage
    const int lchk  = u & 15;            // 16B chunk within the 64-float row
    const float* gsrc = (lm ? m1 : m0) + (size_t)b * (AA * CC)
                        + lrow * CC + lchk * 4;          // advances by 16*CC per stage
    uint32_t ldst[NBUF];
    #pragma unroll
    for (int k = 0; k < NBUF; k++)
        ldst[k] = smem_u32(&buf[k][lm][lrow][lchk * 4]);

    // pre-issue stages 0 and 1 (overlap with the prologue below)
    cp16(ldst[0], gsrc);            cp_commit();
    cp16(ldst[1], gsrc + 16 * CC);  cp_commit();

    // ---------------- phase 1: attn weights ----------------
    float base = 0.0f;
    float diff[DD];
    {
        const float* pa0 = a0 + b * DD;
        const float* pa1 = a1 + b * DD;
        #pragma unroll
        for (int k = 0; k < DD; k++) {
            float x1 = pa1[k];
            base += x1;
            diff[k] = pa0[k] - x1;
        }
    }
    const int jlo = tid;         // low half address
    const int jhi = tid + AA;    // high half address
    float rlo = base, rhi = base;
    #pragma unroll
    for (int k = 0; k < DD; k++) {
        int sh = 9 - k;
        if ((jlo >> sh) & 1) rlo += diff[k];
        if ((jhi >> sh) & 1) rhi += diff[k];
    }

    float maxh = blockReduceMax(rhi, sred);
    float sumh = blockReduceSum(__expf(rhi - maxh), sred);
    const float LOG512 = 6.238324625039508f;   // log(NADDR - A)
    float y2 = maxh + __logf(sumh) - LOG512;

    float mab  = fmaxf(rlo, y2);
    float attn = mab + log1pf(__expf(-fabsf(rlo - y2)));

    float mx  = blockReduceMax(attn, sred);
    float e   = __expf(attn - mx);
    float S   = blockReduceSum(e, sred);
    float ssq = blockReduceSum(e * e, sred);

    sw[tid] = e * (S - e);
    __syncthreads();   // sw visible to all consumers

    // -------- consumer mapping: fixed (m, c4, grp) column per thread --------
    const int grp = tid & 15;            // row-in-stage this thread consumes
    const int c4  = (tid >> 4) & 15;     // float4 channel block
    const int cm  = tid >> 8;            // matrix

    float4 acc = make_float4(0.f, 0.f, 0.f, 0.f);

    #pragma unroll 1
    for (int s = 0; s < NSTAGE; s++) {
        cp_wait1();          // oldest outstanding stage (s) complete (this thread)
        __syncthreads();     // all threads' chunks of stage s visible

        // prefetch stage s+2 into the buffer freed by stage s-1
        if (s + 2 < NSTAGE) {
            cp16(ldst[(s + 2) % NBUF], gsrc + (s + 2) * 16 * CC);
            cp_commit();
        } else {
            cp_commit();     // keep group count in lockstep for wait_group 1
        }

        float  w = sw[s * ROWS_PER_STAGE + grp];
        const float4 x = *reinterpret_cast<const float4*>(&buf[s % NBUF][cm][grp][c4 * 4]);
        acc.x = fmaf(w, __expf(x.x), acc.x);
        acc.y = fmaf(w, __expf(x.y), acc.y);
        acc.z = fmaf(w, __expf(x.z), acc.z);
        acc.w = fmaf(w, __expf(x.w), acc.w);
    }
    cp_wait0();

    // -------- reduce over grp (16 consecutive lanes) via shuffles --------
    #pragma unroll
    for (int o = 8; o; o >>= 1) {
        acc.x += __shfl_xor_sync(0xffffffffu, acc.x, o);
        acc.y += __shfl_xor_sync(0xffffffffu, acc.y, o);
        acc.z += __shfl_xor_sync(0xffffffffu, acc.z, o);
        acc.w += __shfl_xor_sync(0xffffffffu, acc.w, o);
    }

    if (grp == 0) {
        const float* vv = cm ? v1 : v0;
        const int c = c4 * 4;
        float4 r;
        r.x = 2.0f * mx + __logf(acc.x + __expf(vv[b * CC + c + 0]) * ssq);
        r.y = 2.0f * mx + __logf(acc.y + __expf(vv[b * CC + c + 1]) * ssq);
        r.z = 2.0f * mx + __logf(acc.z + __expf(vv[b * CC + c + 2]) * ssq);
        r.w = 2.0f * mx + __logf(acc.w + __expf(vv[b * CC + c + 3]) * ssq);
        *reinterpret_cast<float4*>(out + (size_t)cm * BB * CC + (size_t)b * CC + c) = r;
    }
}

extern "C" void kernel_launch(void* const* d_in, const int* in_sizes, int n_in,
                              void* d_out, int out_size) {
    const float* m0 = (const float*)d_in[0];
    const float* m1 = (const float*)d_in[1];
    const float* a0 = (const float*)d_in[2];
    const float* a1 = (const float*)d_in[3];
    const float* v0 = (const float*)d_in[4];
    const float* v1 = (const float*)d_in[5];
    float* out = (float*)d_out;
    wm_kernel<<<BB, NTH>>>(m0, m1, a0, a1, v0, v1, out);
}